// round 1
// baseline (speedup 1.0000x reference)
#include <cuda_runtime.h>
#include <math.h>

// Problem constants (from reference)
#define BB      65536
#define S_MAX   360
#define EPS_CLP 1e-6f

// One warp per sample. Lanes stride the symmetry set; warp-shuffle argmax
// reduction replicates jnp.argmin tie-breaking over [acos(d), acos(-d)]:
//   - clamp dots BEFORE comparison (so clamp-induced ties break like argmin)
//   - lower index wins on equal value
//   - half0 (acos(d)) wins over half1 (acos(-d)) on equal value
__global__ __launch_bounds__(256)
void quer_loss_kernel(const float* __restrict__ x,
                      const float* __restrict__ y,
                      const int*   __restrict__ n,
                      const float* __restrict__ sym,   // [5, 360, 4]
                      float* __restrict__ out,         // [9*B]: loss | x_near | label_near
                      int B)
{
    const int warp = (blockIdx.x * blockDim.x + threadIdx.x) >> 5;
    const int lane = threadIdx.x & 31;
    if (warp >= B) return;
    const int b = warp;

    const float4 xv = __ldg(reinterpret_cast<const float4*>(x) + b);
    const float4 yv = __ldg(reinterpret_cast<const float4*>(y) + b);
    const int cls   = __ldg(n + b);

    // SYM_COUNTS = [1, 2, 4, 12, 360]
    int c;
    switch (cls) {
        case 0: c = 1;   break;
        case 1: c = 2;   break;
        case 2: c = 4;   break;
        case 3: c = 12;  break;
        default: c = 360; break;
    }

    // normalized prediction
    const float inv = rsqrtf(xv.x*xv.x + xv.y*xv.y + xv.z*xv.z + xv.w*xv.w);
    const float ux = xv.x * inv, uy = xv.y * inv, uz = xv.z * inv, uw = xv.w * inv;

    const float px = yv.x, py = yv.y, pz = yv.z, pw = yv.w;
    const float4* __restrict__ q = reinterpret_cast<const float4*>(sym) + cls * S_MAX;

    // per-lane best over half0 (d) and half1 (-d); clamped dots always > -2
    float best0 = -2.0f; int i0 = 0;
    float best1 = -2.0f; int i1 = 0;

    for (int s = lane; s < c; s += 32) {
        const float4 qv = __ldg(q + s);
        const float qx = qv.x, qy = qv.y, qz = qv.z, qw = qv.w;
        // pos = qua_mul(y, sym)  (xyzw, w last) — exactly the reference formula
        const float rw = qw*pw - qx*px - qy*py - qz*pz;
        const float rx = qw*px + qx*pw + qy*pz - qz*py;
        const float ry = qw*py - qx*pz + qy*pw + qz*px;
        const float rz = qw*pz + qx*py - qy*px + qz*pw;
        float d = ux*rx + uy*ry + uz*rz + uw*rw;
        d = fminf(fmaxf(d, -1.0f + EPS_CLP), 1.0f - EPS_CLP);
        if (d  > best0) { best0 = d;  i0 = s; }   // strict > keeps lowest s
        if (-d > best1) { best1 = -d; i1 = s; }
    }

    // warp argmax reduction: higher value wins; on tie, lower index wins
    #pragma unroll
    for (int off = 16; off > 0; off >>= 1) {
        const float v0 = __shfl_down_sync(0xFFFFFFFFu, best0, off);
        const int   j0 = __shfl_down_sync(0xFFFFFFFFu, i0,   off);
        if (v0 > best0 || (v0 == best0 && j0 < i0)) { best0 = v0; i0 = j0; }
        const float v1 = __shfl_down_sync(0xFFFFFFFFu, best1, off);
        const int   j1 = __shfl_down_sync(0xFFFFFFFFu, i1,   off);
        if (v1 > best1 || (v1 == best1 && j1 < i1)) { best1 = v1; i1 = j1; }
    }

    if (lane == 0) {
        // half0 (acos(d)) wins ties vs half1 (acos(-d)) — argmin order
        const bool half0 = (best0 >= best1);
        const float vbest = half0 ? best0 : best1;
        const int   sbest = half0 ? i0 : i1;

        const float loss = acosf(vbest);

        // recompute winning pos (label_near = pos[j], un-negated, both halves)
        const float4 qv = __ldg(q + sbest);
        const float qx = qv.x, qy = qv.y, qz = qv.z, qw = qv.w;
        const float rw = qw*pw - qx*px - qy*py - qz*pz;
        const float rx = qw*px + qx*pw + qy*pz - qz*py;
        const float ry = qw*py - qx*pz + qy*pw + qz*px;
        const float rz = qw*pz + qx*py - qy*px + qz*pw;

        const float sgn = half0 ? 1.0f : -1.0f;

        out[b] = loss;                                              // loss  [B]
        float4* xn = reinterpret_cast<float4*>(out + B) + b;        // x_near [B,4]
        *xn = make_float4(xv.x*sgn, xv.y*sgn, xv.z*sgn, xv.w*sgn);
        float4* ln = reinterpret_cast<float4*>(out + 5*B) + b;      // label_near [B,4]
        *ln = make_float4(rx, ry, rz, rw);
    }
}

extern "C" void kernel_launch(void* const* d_in, const int* in_sizes, int n_in,
                              void* d_out, int out_size)
{
    // metadata order: x[B,4], y[B,4], pred_n[B,5] (unused), n[B],
    //                 sym_qua[5,360,4], sym_mask[5,360] (unused)
    const float* x   = (const float*)d_in[0];
    const float* y   = (const float*)d_in[1];
    const int*   n   = (const int*)  d_in[3];
    const float* sym = (const float*)d_in[4];
    float* out = (float*)d_out;

    const int B = in_sizes[3];              // 65536
    const int warps_per_block = 8;          // 256 threads
    const int blocks = (B + warps_per_block - 1) / warps_per_block;
    quer_loss_kernel<<<blocks, warps_per_block * 32>>>(x, y, n, sym, out, B);
}

// round 2
// speedup vs baseline: 1.9251x; 1.9251x over previous
#include <cuda_runtime.h>
#include <math.h>

#define S_MAX   360
#define NCLS    5
#define EPS_CLP 1e-6f
#define FULL    0xFFFFFFFFu

// Thread-per-sample for classes with c<=12; warp-cooperative (ballot/ffs)
// handling for c==360 samples. Key identity: dot(u, y (x) q) = (M(y)^T u) . q,
// so each symmetry element costs one 4-wide dot after a per-sample 16-FMA setup.
// Tie-breaking replicates jnp.argmin over concat([acos(d), acos(-d)]):
// clamp before compare, lowest index wins, half0 beats half1 on equal value.
__global__ __launch_bounds__(256)
void quer_loss_kernel(const float*  __restrict__ x,
                      const float*  __restrict__ y,
                      const int*    __restrict__ n,
                      const float4* __restrict__ sym,   // [5*360] float4
                      float* __restrict__ out,          // loss[B] | x_near[B,4] | label_near[B,4]
                      int B)
{
    __shared__ float4 ssym[NCLS * S_MAX];   // 28.8 KB

    const int tid  = threadIdx.x;
    const int lane = tid & 31;

    // stage full symmetry table into smem (once per 256-sample block)
    for (int i = tid; i < NCLS * S_MAX; i += 256)
        ssym[i] = __ldg(sym + i);
    __syncthreads();

    const int b  = blockIdx.x * 256 + tid;
    const bool valid = (b < B);
    const int bl = valid ? b : (B - 1);     // clamped index keeps warp converged

    const float4 xv = __ldg(reinterpret_cast<const float4*>(x) + bl);
    const float4 yv = __ldg(reinterpret_cast<const float4*>(y) + bl);
    const int cls   = __ldg(n + bl);

    // SYM_COUNTS = [1,2,4,12,360]; invalid lanes get c=0 (no work, no ballot hit)
    int c = (cls == 0) ? 1 : (cls == 1) ? 2 : (cls == 2) ? 4 : (cls == 3) ? 12 : 360;
    if (!valid) c = 0;

    // normalized prediction u
    const float inv = rsqrtf(xv.x*xv.x + xv.y*xv.y + xv.z*xv.z + xv.w*xv.w);
    const float ux = xv.x * inv, uy = xv.y * inv, uz = xv.z * inv, uw = xv.w * inv;

    // v = M(y)^T u  so that dot(u, qua_mul(y, q)) == v . q
    const float px = yv.x, py = yv.y, pz = yv.z, pw = yv.w;
    const float vx =  ux*pw - uy*pz + uz*py - uw*px;
    const float vy =  ux*pz + uy*pw - uz*px - uw*py;
    const float vz = -ux*py + uy*px + uz*pw - uw*pz;
    const float vw =  ux*px + uy*py + uz*pz + uw*pw;

    float best0 = -2.0f, best1 = -2.0f;
    int   i0 = 0, i1 = 0;

    const float4* __restrict__ tab = ssym + cls * S_MAX;

    // ---- small-class phase: each thread scans its own c<=12 set ----
    if (c <= 12) {
        for (int s = 0; s < c; ++s) {
            const float4 q = tab[s];
            float d = vx*q.x + vy*q.y + vz*q.z + vw*q.w;
            d = fminf(fmaxf(d, -1.0f + EPS_CLP), 1.0f - EPS_CLP);
            if ( d > best0) { best0 =  d; i0 = s; }   // strict > keeps lowest s
            if (-d > best1) { best1 = -d; i1 = s; }
        }
    }

    // ---- cooperative phase: warp jointly scans each c==360 sample ----
    unsigned coop = __ballot_sync(FULL, c == 360);
    const float4* __restrict__ tab4 = ssym + 4 * S_MAX;
    while (coop) {
        const int leader = __ffs(coop) - 1;
        coop &= coop - 1;

        const float wvx = __shfl_sync(FULL, vx, leader);
        const float wvy = __shfl_sync(FULL, vy, leader);
        const float wvz = __shfl_sync(FULL, vz, leader);
        const float wvw = __shfl_sync(FULL, vw, leader);

        float bb0 = -2.0f, bb1 = -2.0f;
        int   j0 = 0, j1 = 0;
        #pragma unroll
        for (int k = 0; k < 12; ++k) {
            const int s = lane + k * 32;
            if (s < S_MAX) {
                const float4 q = tab4[s];
                float d = wvx*q.x + wvy*q.y + wvz*q.z + wvw*q.w;
                d = fminf(fmaxf(d, -1.0f + EPS_CLP), 1.0f - EPS_CLP);
                if ( d > bb0) { bb0 =  d; j0 = s; }
                if (-d > bb1) { bb1 = -d; j1 = s; }
            }
        }
        // warp argmax (higher value wins; tie -> lower index)
        #pragma unroll
        for (int off = 16; off > 0; off >>= 1) {
            const float t0 = __shfl_down_sync(FULL, bb0, off);
            const int   k0 = __shfl_down_sync(FULL, j0,  off);
            if (t0 > bb0 || (t0 == bb0 && k0 < j0)) { bb0 = t0; j0 = k0; }
            const float t1 = __shfl_down_sync(FULL, bb1, off);
            const int   k1 = __shfl_down_sync(FULL, j1,  off);
            if (t1 > bb1 || (t1 == bb1 && k1 < j1)) { bb1 = t1; j1 = k1; }
        }
        // broadcast result to the owning lane
        const float r0 = __shfl_sync(FULL, bb0, 0);
        const int   s0 = __shfl_sync(FULL, j0,  0);
        const float r1 = __shfl_sync(FULL, bb1, 0);
        const int   s1 = __shfl_sync(FULL, j1,  0);
        if (lane == leader) { best0 = r0; i0 = s0; best1 = r1; i1 = s1; }
    }

    if (!valid) return;

    // ---- epilogue: every thread finalizes its own sample ----
    const bool  half0 = (best0 >= best1);     // half0 wins ties (argmin order)
    const float vbest = half0 ? best0 : best1;
    const int   sbest = half0 ? i0 : i1;

    const float loss = acosf(vbest);

    // recompute winning pos = qua_mul(y, sym[cls][sbest]) with reference formula
    const float4 q = tab[sbest];
    const float qx = q.x, qy = q.y, qz = q.z, qw = q.w;
    const float rw = qw*pw - qx*px - qy*py - qz*pz;
    const float rx = qw*px + qx*pw + qy*pz - qz*py;
    const float ry = qw*py - qx*pz + qy*pw + qz*px;
    const float rz = qw*pz + qx*py - qy*px + qz*pw;

    const float sgn = half0 ? 1.0f : -1.0f;

    out[b] = loss;
    reinterpret_cast<float4*>(out + B)[b]     = make_float4(xv.x*sgn, xv.y*sgn, xv.z*sgn, xv.w*sgn);
    reinterpret_cast<float4*>(out + 5*B)[b]   = make_float4(rx, ry, rz, rw);
}

extern "C" void kernel_launch(void* const* d_in, const int* in_sizes, int n_in,
                              void* d_out, int out_size)
{
    // metadata order: x[B,4], y[B,4], pred_n[B,5] (unused), n[B],
    //                 sym_qua[5,360,4], sym_mask[5,360] (unused)
    const float*  x   = (const float*) d_in[0];
    const float*  y   = (const float*) d_in[1];
    const int*    n   = (const int*)   d_in[3];
    const float4* sym = (const float4*)d_in[4];
    float* out = (float*)d_out;

    const int B = in_sizes[3];                    // 65536
    const int blocks = (B + 255) / 256;
    quer_loss_kernel<<<blocks, 256>>>(x, y, n, sym, out, B);
}